// round 10
// baseline (speedup 1.0000x reference)
#include <cuda_runtime.h>
#include <cuda_fp16.h>
#include <cstdint>
#include <cstddef>

// Problem constants (fixed by setup_inputs)
#define BB    8
#define N1    8192
#define M2    2048
#define C1    128
#define C2    256
#define CIN   384
#define H0    256
#define H1    128
#define NPTS  (BB * N1)   // 65536

// knn block geometry: 128 threads handle 128 points -> 64 blocks/batch
#define KNN_PTS   128
#define KNN_BLKS  (N1 / KNN_PTS)   // 64

// ---------------- scratch (device globals; no allocations allowed) ----------
__device__ __align__(16) __half g_fh[(size_t)NPTS * CIN];   // feat fp16
__device__ __align__(16) __half g_w0h[H0 * CIN];            // w0 fp16
__device__ __align__(16) __half g_w1h[H1 * H0];             // w1 fp16
__device__ __align__(16) __half g_h1[(size_t)NPTS * H0];    // h1 fp16
__device__ float g_scale0[BB * H0];
__device__ float g_shift0[BB * H0];
__device__ float g_scale1[BB * H1];
__device__ float g_shift1[BB * H1];
__device__ float g_s0[BB * H0];
__device__ float g_q0[BB * H0];
__device__ float g_s1[BB * H1];
__device__ float g_q1[BB * H1];
__device__ int   g_cnt0[BB];
__device__ int   g_cnt1[BB];

// ---------------- PTX helpers ------------------------------------------------
__device__ __forceinline__ uint32_t smem_u32(const void* p) {
    uint32_t a;
    asm("{ .reg .u64 t; cvta.to.shared.u64 t, %1; cvt.u32.u64 %0, t; }"
        : "=r"(a) : "l"(p));
    return a;
}
__device__ __forceinline__ void cpa16(uint32_t dst, const void* src) {
    asm volatile("cp.async.cg.shared.global [%0], [%1], 16;"
                 :: "r"(dst), "l"(src) : "memory");
}
#define CP_COMMIT() asm volatile("cp.async.commit_group;" ::: "memory")
#define CP_WAIT(n)  asm volatile("cp.async.wait_group %0;" :: "n"(n) : "memory")

__device__ __forceinline__ void ldsm4(uint32_t& r0, uint32_t& r1,
                                      uint32_t& r2, uint32_t& r3, uint32_t a) {
    asm volatile("ldmatrix.sync.aligned.m8n8.x4.shared.b16 {%0,%1,%2,%3}, [%4];"
                 : "=r"(r0), "=r"(r1), "=r"(r2), "=r"(r3) : "r"(a));
}
__device__ __forceinline__ void mma16816(float* c, const uint32_t* a,
                                         uint32_t b0, uint32_t b1) {
    asm volatile(
        "mma.sync.aligned.m16n8k16.row.col.f32.f16.f16.f32 "
        "{%0,%1,%2,%3}, {%4,%5,%6,%7}, {%8,%9}, {%0,%1,%2,%3};"
        : "+f"(c[0]), "+f"(c[1]), "+f"(c[2]), "+f"(c[3])
        : "r"(a[0]), "r"(a[1]), "r"(a[2]), "r"(a[3]), "r"(b0), "r"(b1));
}
__device__ __forceinline__ uint32_t h2bits(__half2 v) {
    return *reinterpret_cast<uint32_t*>(&v);
}

// ---------------- fp16 GEMM on mma.sync + fused GN stats + fused scale ------
// C[m,n] = sum_k A'[m,k] * W[n,k]; block tile 128 x NOUT, 512 threads.
// MODE 0: A fp16 via cp.async; C written fp16.
// MODE 1: A fp16 + GN fold (smem-cached scale/shift) + relu at load; C fp32.
template <int K, int NOUT, int MODE>
__global__ __launch_bounds__(512, 1) void mma_gemm(
    const __half* __restrict__ Ah, const __half* __restrict__ Af,
    const __half* __restrict__ Bh,
    void* __restrict__ Cv,
    const float* __restrict__ scale, const float* __restrict__ shift,
    float* __restrict__ statS, float* __restrict__ statQ,
    const float* __restrict__ gw, const float* __restrict__ gb,
    float* __restrict__ oScale, float* __restrict__ oShift,
    int* __restrict__ counter)
{
    constexpr int CH = K / 64;
    constexpr int WN = NOUT / 8;
    constexpr int NT = WN / 8;
    constexpr int APLANE = 16384;
    constexpr int BPLANE = NOUT * 128;
    constexpr int STAGE = APLANE + BPLANE;
    constexpr int BITER = NOUT / 64;
    constexpr int CPG = NOUT / 32;

    extern __shared__ __align__(128) char smem[];
    const uint32_t sb = smem_u32(smem);
    float* sS = (float*)(smem + 2 * STAGE);
    float* sQ = sS + NOUT;
    float* sScale = sQ + NOUT;            // [K] (MODE 1)
    float* sShift = sScale + K;
    const int t = threadIdx.x;
    const int wid = t >> 5, lane = t & 31;
    const int warpM = (wid >> 3) * 64;
    const int warpN = (wid & 7) * WN;
    const int row0 = blockIdx.x * 128;
    const int b = row0 >> 13;

    if (t < NOUT) { sS[t] = 0.f; sQ[t] = 0.f; }
    if (MODE == 1) {
        if (t < K) { sScale[t] = scale[b * K + t]; sShift[t] = shift[b * K + t]; }
        __syncthreads();
    }

    float acc[4][NT][4];
#pragma unroll
    for (int i = 0; i < 4; ++i)
#pragma unroll
        for (int j = 0; j < NT; ++j)
#pragma unroll
            for (int q = 0; q < 4; ++q) acc[i][j][q] = 0.f;

    float va[2][8];

    auto issueB = [&](int c, int s) {
#pragma unroll
        for (int i = 0; i < BITER; ++i) {
            const int id = t + i * 512;
            const int n = id >> 3, a = id & 7;
            const uint32_t swo = (uint32_t)(a * 16) ^ (uint32_t)((n & 7) << 4);
            cpa16(sb + s * STAGE + APLANE + n * 128 + swo,
                  Bh + (size_t)n * K + c * 64 + a * 8);
        }
    };
    auto issueA = [&](int c, int s) {
#pragma unroll
        for (int i = 0; i < 2; ++i) {
            const int id = t + i * 512;
            const int r = id >> 3, a = id & 7;
            const uint32_t swo = (uint32_t)(a * 16) ^ (uint32_t)((r & 7) << 4);
            cpa16(sb + s * STAGE + r * 128 + swo,
                  Ah + (size_t)(row0 + r) * K + c * 64 + a * 8);
        }
    };
    auto ldgA = [&](int c) {
#pragma unroll
        for (int i = 0; i < 2; ++i) {
            const int id = t + i * 512;
            const int r = id >> 3, a = id & 7;
            const uint4 raw = *(const uint4*)(Af + (size_t)(row0 + r) * K + c * 64 + a * 8);
            const __half2* hp = (const __half2*)&raw;
            const float2 f0 = __half22float2(hp[0]);
            const float2 f1 = __half22float2(hp[1]);
            const float2 f2 = __half22float2(hp[2]);
            const float2 f3 = __half22float2(hp[3]);
            const int col = c * 64 + a * 8;
            const float4 s0 = *(const float4*)(sScale + col);
            const float4 s1 = *(const float4*)(sScale + col + 4);
            const float4 h0 = *(const float4*)(sShift + col);
            const float4 h1 = *(const float4*)(sShift + col + 4);
            va[i][0] = fmaxf(0.f, fmaf(f0.x, s0.x, h0.x));
            va[i][1] = fmaxf(0.f, fmaf(f0.y, s0.y, h0.y));
            va[i][2] = fmaxf(0.f, fmaf(f1.x, s0.z, h0.z));
            va[i][3] = fmaxf(0.f, fmaf(f1.y, s0.w, h0.w));
            va[i][4] = fmaxf(0.f, fmaf(f2.x, s1.x, h1.x));
            va[i][5] = fmaxf(0.f, fmaf(f2.y, s1.y, h1.y));
            va[i][6] = fmaxf(0.f, fmaf(f3.x, s1.z, h1.z));
            va[i][7] = fmaxf(0.f, fmaf(f3.y, s1.w, h1.w));
        }
    };
    auto stsA = [&](int s) {
#pragma unroll
        for (int i = 0; i < 2; ++i) {
            const int id = t + i * 512;
            const int r = id >> 3, a = id & 7;
            uint32_t hw[4];
#pragma unroll
            for (int q = 0; q < 4; ++q)
                hw[q] = h2bits(__floats2half2_rn(va[i][2 * q], va[i][2 * q + 1]));
            const uint32_t swo = (uint32_t)(a * 16) ^ (uint32_t)((r & 7) << 4);
            asm volatile("st.shared.v4.b32 [%0], {%1,%2,%3,%4};"
                         :: "r"(sb + s * STAGE + r * 128 + swo),
                            "r"(hw[0]), "r"(hw[1]), "r"(hw[2]), "r"(hw[3]) : "memory");
        }
    };

    if (MODE == 1) { ldgA(0); issueB(0, 0); CP_COMMIT(); }
    else           { issueA(0, 0); issueB(0, 0); CP_COMMIT(); }

    for (int c = 0; c < CH; ++c) {
        const int s = c & 1;
        if (MODE == 1) {
            stsA(s);
            if (c + 1 < CH) { issueB(c + 1, s ^ 1); CP_COMMIT(); CP_WAIT(1); }
            else            { CP_WAIT(0); }
            __syncthreads();
            if (c + 1 < CH) ldgA(c + 1);
        } else {
            if (c + 1 < CH) {
                issueA(c + 1, s ^ 1);
                issueB(c + 1, s ^ 1);
                CP_COMMIT();
                CP_WAIT(1);
            } else {
                CP_WAIT(0);
            }
            __syncthreads();
        }

        const uint32_t aB = sb + s * STAGE;
        const uint32_t bB = aB + APLANE;

        const int rowL = lane & 15;
        const uint32_t xorA = (uint32_t)((rowL & 7) << 4);
        const uint32_t colA0 = (uint32_t)((lane >> 4) * 16);
        const int nl = ((lane >> 4) << 3) + (lane & 7);
        const uint32_t xorB = (uint32_t)((nl & 7) << 4);
        const uint32_t colB0 = (uint32_t)(((lane >> 3) & 1) * 16);

#pragma unroll
        for (int s16 = 0; s16 < 4; ++s16) {
#pragma unroll
            for (int mth = 0; mth < 2; ++mth) {
                uint32_t af[2][4];
#pragma unroll
                for (int q = 0; q < 2; ++q) {
                    const int mt = mth * 2 + q;
                    const uint32_t off = (uint32_t)(warpM + mt * 16 + rowL) * 128 +
                                         ((colA0 + s16 * 32) ^ xorA);
                    ldsm4(af[q][0], af[q][1], af[q][2], af[q][3], aB + off);
                }
#pragma unroll
                for (int np = 0; np < NT / 2; ++np) {
                    const uint32_t offB = (uint32_t)(warpN + np * 16 + nl) * 128 +
                                          ((colB0 + s16 * 32) ^ xorB);
                    uint32_t b0, b1, b2, b3;
                    ldsm4(b0, b1, b2, b3, bB + offB);
#pragma unroll
                    for (int q = 0; q < 2; ++q)
                        mma16816(acc[mth * 2 + q][2 * np], af[q], b0, b1);
#pragma unroll
                    for (int q = 0; q < 2; ++q)
                        mma16816(acc[mth * 2 + q][2 * np + 1], af[q], b2, b3);
                }
            }
        }
        __syncthreads();
    }

    // ---- epilogue: write C + per-column stats ----
    const int g = lane >> 2, tig = lane & 3;
    if (MODE == 0) {
        __half* Ch = (__half*)Cv;
#pragma unroll
        for (int mt = 0; mt < 4; ++mt) {
#pragma unroll
            for (int nt = 0; nt < NT; ++nt) {
                const int row = row0 + warpM + mt * 16 + g;
                const int col = warpN + nt * 8 + tig * 2;
                *(uint32_t*)(Ch + (size_t)row * NOUT + col) =
                    h2bits(__floats2half2_rn(acc[mt][nt][0], acc[mt][nt][1]));
                *(uint32_t*)(Ch + (size_t)(row + 8) * NOUT + col) =
                    h2bits(__floats2half2_rn(acc[mt][nt][2], acc[mt][nt][3]));
            }
        }
    } else {
        float* Cf = (float*)Cv;
#pragma unroll
        for (int mt = 0; mt < 4; ++mt) {
#pragma unroll
            for (int nt = 0; nt < NT; ++nt) {
                const int row = row0 + warpM + mt * 16 + g;
                const int col = warpN + nt * 8 + tig * 2;
                *(float2*)(Cf + (size_t)row * NOUT + col) =
                    make_float2(acc[mt][nt][0], acc[mt][nt][1]);
                *(float2*)(Cf + (size_t)(row + 8) * NOUT + col) =
                    make_float2(acc[mt][nt][2], acc[mt][nt][3]);
            }
        }
    }
#pragma unroll
    for (int nt = 0; nt < NT; ++nt) {
        float s0 = 0.f, s1 = 0.f, q0 = 0.f, q1 = 0.f;
#pragma unroll
        for (int mt = 0; mt < 4; ++mt) {
            const float a0 = acc[mt][nt][0], a1 = acc[mt][nt][1];
            const float a2 = acc[mt][nt][2], a3 = acc[mt][nt][3];
            s0 += a0 + a2;  s1 += a1 + a3;
            q0 += a0 * a0 + a2 * a2;
            q1 += a1 * a1 + a3 * a3;
        }
#pragma unroll
        for (int o = 4; o < 32; o <<= 1) {
            s0 += __shfl_xor_sync(~0u, s0, o);
            s1 += __shfl_xor_sync(~0u, s1, o);
            q0 += __shfl_xor_sync(~0u, q0, o);
            q1 += __shfl_xor_sync(~0u, q1, o);
        }
        if (g == 0) {
            const int col = warpN + nt * 8 + tig * 2;
            atomicAdd(&sS[col], s0);  atomicAdd(&sS[col + 1], s1);
            atomicAdd(&sQ[col], q0);  atomicAdd(&sQ[col + 1], q1);
        }
    }
    __syncthreads();
    if (t < NOUT) {
        atomicAdd(statS + b * NOUT + t, sS[t]);
        atomicAdd(statQ + b * NOUT + t, sQ[t]);
        __threadfence();
    }
    __syncthreads();

    __shared__ int sLast;
    if (t == 0) sLast = (atomicAdd(&counter[b], 1) == 63);
    __syncthreads();
    if (sLast && t < NOUT) {
        const float s = *(volatile float*)(statS + b * NOUT + t);
        const float q = *(volatile float*)(statQ + b * NOUT + t);
        float gs = s, gq = q;
#pragma unroll
        for (int o = CPG >> 1; o; o >>= 1) {
            gs += __shfl_xor_sync(~0u, gs, o);
            gq += __shfl_xor_sync(~0u, gq, o);
        }
        const float cnt = (float)N1 * (float)CPG;
        const float mean = gs / cnt;
        const float var  = gq / cnt - mean * mean;
        const float rstd = rsqrtf(var + 1e-5f);
        const float sc = rstd * gw[t];
        oScale[b * NOUT + t] = sc;
        oShift[b * NOUT + t] = gb[t] - mean * sc;
    }
}

// ---------------- knn + interpolate (128-thread blocks for chip balance) ----
__global__ __launch_bounds__(128) void knn_interp_kernel(
    const float* __restrict__ xyz1, const float* __restrict__ xyz2,
    const float* __restrict__ points1, const float* __restrict__ points2,
    const float* __restrict__ w0src, const float* __restrict__ w1src)
{
    const int b = blockIdx.y;

    if (blockIdx.x == KNN_BLKS) {   // prep slice: weights + zero accums
        const int t = threadIdx.x;
        for (int i = b * (H0 * CIN / BB) + t; i < (b + 1) * (H0 * CIN / BB); i += 128)
            g_w0h[i] = __float2half_rn(w0src[i]);
        for (int i = b * (H1 * H0 / BB) + t; i < (b + 1) * (H1 * H0 / BB); i += 128)
            g_w1h[i] = __float2half_rn(w1src[i]);
        if (b == 0) {
            for (int i = t; i < BB * H0; i += 128) { g_s0[i] = 0.f; g_q0[i] = 0.f; }
            for (int i = t; i < BB * H1; i += 128) { g_s1[i] = 0.f; g_q1[i] = 0.f; }
            if (t < BB) { g_cnt0[t] = 0; g_cnt1[t] = 0; }
        }
        return;
    }

    // smem candidate: (-2x, -2y, -2z, |q|^2) so d' = 3 chained FMAs.
    __shared__ float4 sp[M2];                        // 32 KB
    __shared__ float sW0[KNN_PTS], sW1[KNN_PTS], sW2[KNN_PTS];
    __shared__ int   sI0[KNN_PTS], sI1[KNN_PTS], sI2[KNN_PTS];
    const float* x2 = xyz2 + (size_t)b * M2 * 3;
    for (int j = threadIdx.x; j < M2; j += 128) {
        float x = x2[j * 3 + 0], y = x2[j * 3 + 1], z = x2[j * 3 + 2];
        sp[j] = make_float4(-2.f * x, -2.f * y, -2.f * z, x * x + y * y + z * z);
    }
    __syncthreads();

    // ---- phase 1: per-thread top-3 scan ----
    const int n = blockIdx.x * KNN_PTS + threadIdx.x;
    const float* p1 = xyz1 + ((size_t)b * N1 + n) * 3;
    const float px = p1[0], py = p1[1], pz = p1[2];
    const float psq = px * px + py * py + pz * pz;

    float d0 = 1e30f, d1 = 1e30f, d2 = 1e30f;
    int i0 = 0, i1 = 0, i2 = 0;
    auto insert = [&](float d, int j) {
        if (d < d2) {
            if (d < d1) {
                if (d < d0) { d2 = d1; i2 = i1; d1 = d0; i1 = i0; d0 = d; i0 = j; }
                else        { d2 = d1; i2 = i1; d1 = d;  i1 = j; }
            } else          { d2 = d;  i2 = j; }
        }
    };
#pragma unroll 4
    for (int j = 0; j < M2; j += 2) {
        const float4 qa = sp[j];
        const float4 qb = sp[j + 1];
        const float da = fmaf(px, qa.x, fmaf(py, qa.y, fmaf(pz, qa.z, qa.w)));
        const float db = fmaf(px, qb.x, fmaf(py, qb.y, fmaf(pz, qb.z, qb.w)));
        if (fminf(da, db) < d2) { insert(da, j); insert(db, j + 1); }
    }

    {
        float w0 = 1.0f / ((d0 + psq) + 1e-8f);
        float w1 = 1.0f / ((d1 + psq) + 1e-8f);
        float w2 = 1.0f / ((d2 + psq) + 1e-8f);
        const float inv = 1.0f / (w0 + w1 + w2);
        sW0[threadIdx.x] = w0 * inv;
        sW1[threadIdx.x] = w1 * inv;
        sW2[threadIdx.x] = w2 * inv;
        sI0[threadIdx.x] = i0;
        sI1[threadIdx.x] = i1;
        sI2[threadIdx.x] = i2;
    }
    __syncthreads();

    // ---- phase 2: warp-cooperative gather + interpolate + concat ----
    const int lane = threadIdx.x & 31, w = threadIdx.x >> 5;
    const size_t mbase = (size_t)b * N1 + blockIdx.x * KNN_PTS;
    const float* p2base = points2 + (size_t)b * M2 * C2;

#pragma unroll 2
    for (int pp = 0; pp < 32; ++pp) {
        const int p = w * 32 + pp;
        const size_t m = mbase + p;
        __half* fhp = g_fh + m * CIN;

        // points1 copy: lane owns 4 floats (fully coalesced)
        const float4 u = *(const float4*)(points1 + m * C1 + lane * 4);
        const uint32_t c01 = h2bits(__floats2half2_rn(u.x, u.y));
        const uint32_t c23 = h2bits(__floats2half2_rn(u.z, u.w));
        *(uint2*)(fhp + lane * 4) = make_uint2(c01, c23);

        // interpolation: lane owns 8 of 256 channels (fully coalesced rows)
        const float w0 = sW0[p], w1 = sW1[p], w2 = sW2[p];
        const float* r0 = p2base + (size_t)sI0[p] * C2 + lane * 8;
        const float* r1 = p2base + (size_t)sI1[p] * C2 + lane * 8;
        const float* r2 = p2base + (size_t)sI2[p] * C2 + lane * 8;
        uint32_t oh[4];
#pragma unroll
        for (int h = 0; h < 2; ++h) {
            const float4 a  = *(const float4*)(r0 + h * 4);
            const float4 bb = *(const float4*)(r1 + h * 4);
            const float4 cc = *(const float4*)(r2 + h * 4);
            const float o0 = w0 * a.x + w1 * bb.x + w2 * cc.x;
            const float o1 = w0 * a.y + w1 * bb.y + w2 * cc.y;
            const float o2 = w0 * a.z + w1 * bb.z + w2 * cc.z;
            const float o3 = w0 * a.w + w1 * bb.w + w2 * cc.w;
            oh[h * 2 + 0] = h2bits(__floats2half2_rn(o0, o1));
            oh[h * 2 + 1] = h2bits(__floats2half2_rn(o2, o3));
        }
        *(uint4*)(fhp + C1 + lane * 8) = make_uint4(oh[0], oh[1], oh[2], oh[3]);
    }
}

// ---------------- final GN1 + ReLU in-place on d_out ------------------------
__global__ __launch_bounds__(256) void apply_kernel(
    float* __restrict__ out,
    const float* __restrict__ scale, const float* __restrict__ shift)
{
    const int lane = threadIdx.x & 31, w = threadIdx.x >> 5;
    const int row0 = blockIdx.x * 32;
    const int b = row0 >> 13;
    const int col = lane * 4;
    const float4 sc = *(const float4*)(scale + b * H1 + col);
    const float4 sh = *(const float4*)(shift + b * H1 + col);
#pragma unroll
    for (int i = 0; i < 4; ++i) {
        float* p = out + (size_t)(row0 + w * 4 + i) * H1 + col;
        float4 v = *(float4*)p;
        v.x = fmaxf(0.f, fmaf(v.x, sc.x, sh.x));
        v.y = fmaxf(0.f, fmaf(v.y, sc.y, sh.y));
        v.z = fmaxf(0.f, fmaf(v.z, sc.z, sh.z));
        v.w = fmaxf(0.f, fmaf(v.w, sc.w, sh.w));
        *(float4*)p = v;
    }
}

// ---------------- launcher ---------------------------------------------------
extern "C" void kernel_launch(void* const* d_in, const int* in_sizes, int n_in,
                              void* d_out, int out_size)
{
    const float* xyz1    = (const float*)d_in[0];
    const float* xyz2    = (const float*)d_in[1];
    const float* points1 = (const float*)d_in[2];
    const float* points2 = (const float*)d_in[3];
    const float* w0      = (const float*)d_in[4];
    const float* w1      = (const float*)d_in[5];
    const float* gn0w    = (const float*)d_in[6];
    const float* gn0b    = (const float*)d_in[7];
    const float* gn1w    = (const float*)d_in[8];
    const float* gn1b    = (const float*)d_in[9];
    float* out = (float*)d_out;

    __half *fh, *w0h, *w1h, *h1;
    float *sc0, *sh0, *sc1, *sh1, *s0, *q0, *s1, *q1;
    int *c0, *c1;
    cudaGetSymbolAddress((void**)&fh,  g_fh);
    cudaGetSymbolAddress((void**)&w0h, g_w0h);
    cudaGetSymbolAddress((void**)&w1h, g_w1h);
    cudaGetSymbolAddress((void**)&h1,  g_h1);
    cudaGetSymbolAddress((void**)&sc0, g_scale0);
    cudaGetSymbolAddress((void**)&sh0, g_shift0);
    cudaGetSymbolAddress((void**)&sc1, g_scale1);
    cudaGetSymbolAddress((void**)&sh1, g_shift1);
    cudaGetSymbolAddress((void**)&s0,  g_s0);
    cudaGetSymbolAddress((void**)&q0,  g_q0);
    cudaGetSymbolAddress((void**)&s1,  g_s1);
    cudaGetSymbolAddress((void**)&q1,  g_q1);
    cudaGetSymbolAddress((void**)&c0,  g_cnt0);
    cudaGetSymbolAddress((void**)&c1,  g_cnt1);

    const int SMEM1 = 2 * (16384 + H0 * 128) + 2 * H0 * 4 + 2 * CIN * 4;
    const int SMEM2 = 2 * (16384 + H1 * 128) + 2 * H1 * 4 + 2 * H0 * 4;
    cudaFuncSetAttribute(mma_gemm<CIN, H0, 0>,
                         cudaFuncAttributeMaxDynamicSharedMemorySize, SMEM1);
    cudaFuncSetAttribute(mma_gemm<H0, H1, 1>,
                         cudaFuncAttributeMaxDynamicSharedMemorySize, SMEM2);

    // 1) knn interp + concat: 512 compute blocks (+8 prep) for chip balance
    knn_interp_kernel<<<dim3(KNN_BLKS + 1, BB), 128>>>(
        xyz1, xyz2, points1, points2, w0, w1);

    // 2) h1(fp16) = feat @ w0^T; fused GN0 stats + scale fold
    mma_gemm<CIN, H0, 0><<<NPTS / 128, 512, SMEM1>>>(
        fh, nullptr, w0h, h1, nullptr, nullptr,
        s0, q0, gn0w, gn0b, sc0, sh0, c0);

    // 3) out(fp32) = relu(gn0(h1)) @ w1^T; fused GN1 stats
    mma_gemm<H0, H1, 1><<<NPTS / 128, 512, SMEM2>>>(
        nullptr, h1, w1h, out, sc0, sh0,
        s1, q1, gn1w, gn1b, sc1, sh1, c1);

    // 4) GN1 + ReLU in-place (fixed-channel mapping)
    apply_kernel<<<NPTS / 32, 256>>>(out, sc1, sh1);
}

// round 11
// speedup vs baseline: 1.0303x; 1.0303x over previous
#include <cuda_runtime.h>
#include <cuda_fp16.h>
#include <cstdint>
#include <cstddef>

// Problem constants (fixed by setup_inputs)
#define BB    8
#define N1    8192
#define M2    2048
#define C1    128
#define C2    256
#define CIN   384
#define H0    256
#define H1    128
#define NPTS  (BB * N1)   // 65536

#define NSM   148          // persistent grid size (<= GB300 152 SMs)

// ---------------- scratch (device globals; no allocations allowed) ----------
__device__ __align__(16) __half g_fh[(size_t)NPTS * CIN];   // feat fp16
__device__ __align__(16) __half g_w0h[H0 * CIN];            // w0 fp16
__device__ __align__(16) __half g_w1h[H1 * H0];             // w1 fp16
__device__ __align__(16) __half g_h1[(size_t)NPTS * H0];    // h1 fp16
__device__ float g_scale0[BB * H0];
__device__ float g_shift0[BB * H0];
__device__ float g_s0[BB * H0];
__device__ float g_q0[BB * H0];
__device__ float g_s1[BB * H1];
__device__ float g_q1[BB * H1];
__device__ int   g_cnt0[BB];
__device__ int   g_done;

// ---------------- PTX helpers ------------------------------------------------
__device__ __forceinline__ uint32_t smem_u32(const void* p) {
    uint32_t a;
    asm("{ .reg .u64 t; cvta.to.shared.u64 t, %1; cvt.u32.u64 %0, t; }"
        : "=r"(a) : "l"(p));
    return a;
}
__device__ __forceinline__ void cpa16(uint32_t dst, const void* src) {
    asm volatile("cp.async.cg.shared.global [%0], [%1], 16;"
                 :: "r"(dst), "l"(src) : "memory");
}
#define CP_COMMIT() asm volatile("cp.async.commit_group;" ::: "memory")
#define CP_WAIT(n)  asm volatile("cp.async.wait_group %0;" :: "n"(n) : "memory")

__device__ __forceinline__ void ldsm4(uint32_t& r0, uint32_t& r1,
                                      uint32_t& r2, uint32_t& r3, uint32_t a) {
    asm volatile("ldmatrix.sync.aligned.m8n8.x4.shared.b16 {%0,%1,%2,%3}, [%4];"
                 : "=r"(r0), "=r"(r1), "=r"(r2), "=r"(r3) : "r"(a));
}
__device__ __forceinline__ void mma16816(float* c, const uint32_t* a,
                                         uint32_t b0, uint32_t b1) {
    asm volatile(
        "mma.sync.aligned.m16n8k16.row.col.f32.f16.f16.f32 "
        "{%0,%1,%2,%3}, {%4,%5,%6,%7}, {%8,%9}, {%0,%1,%2,%3};"
        : "+f"(c[0]), "+f"(c[1]), "+f"(c[2]), "+f"(c[3])
        : "r"(a[0]), "r"(a[1]), "r"(a[2]), "r"(a[3]), "r"(b0), "r"(b1));
}
__device__ __forceinline__ uint32_t h2bits(__half2 v) {
    return *reinterpret_cast<uint32_t*>(&v);
}

// ---------------- GEMM1: fp16 mma.sync + fused GN0 stats + scale fold -------
// h1[m,n] = sum_k feat[m,k] * w0[n,k]; 512 threads, tile 128 x 256.
__global__ __launch_bounds__(512, 1) void mma_gemm1(
    const __half* __restrict__ Ah, const __half* __restrict__ Bh,
    __half* __restrict__ C,
    float* __restrict__ statS, float* __restrict__ statQ,
    const float* __restrict__ gw, const float* __restrict__ gb,
    float* __restrict__ oScale, float* __restrict__ oShift,
    int* __restrict__ counter)
{
    constexpr int K = CIN, NOUT = H0;
    constexpr int CH = K / 64;
    constexpr int WN = NOUT / 8;
    constexpr int NT = WN / 8;
    constexpr int APLANE = 16384;
    constexpr int BPLANE = NOUT * 128;
    constexpr int STAGE = APLANE + BPLANE;
    constexpr int BITER = NOUT / 64;
    constexpr int CPG = NOUT / 32;

    extern __shared__ __align__(128) char smem[];
    const uint32_t sb = smem_u32(smem);
    float* sS = (float*)(smem + 2 * STAGE);
    float* sQ = sS + NOUT;
    const int t = threadIdx.x;
    const int wid = t >> 5, lane = t & 31;
    const int warpM = (wid >> 3) * 64;
    const int warpN = (wid & 7) * WN;
    const int row0 = blockIdx.x * 128;
    const int b = row0 >> 13;

    if (t < NOUT) { sS[t] = 0.f; sQ[t] = 0.f; }

    float acc[4][NT][4];
#pragma unroll
    for (int i = 0; i < 4; ++i)
#pragma unroll
        for (int j = 0; j < NT; ++j)
#pragma unroll
            for (int q = 0; q < 4; ++q) acc[i][j][q] = 0.f;

    auto issueB = [&](int c, int s) {
#pragma unroll
        for (int i = 0; i < BITER; ++i) {
            const int id = t + i * 512;
            const int n = id >> 3, a = id & 7;
            const uint32_t swo = (uint32_t)(a * 16) ^ (uint32_t)((n & 7) << 4);
            cpa16(sb + s * STAGE + APLANE + n * 128 + swo,
                  Bh + (size_t)n * K + c * 64 + a * 8);
        }
    };
    auto issueA = [&](int c, int s) {
#pragma unroll
        for (int i = 0; i < 2; ++i) {
            const int id = t + i * 512;
            const int r = id >> 3, a = id & 7;
            const uint32_t swo = (uint32_t)(a * 16) ^ (uint32_t)((r & 7) << 4);
            cpa16(sb + s * STAGE + r * 128 + swo,
                  Ah + (size_t)(row0 + r) * K + c * 64 + a * 8);
        }
    };

    issueA(0, 0); issueB(0, 0); CP_COMMIT();

    for (int c = 0; c < CH; ++c) {
        const int s = c & 1;
        if (c + 1 < CH) {
            issueA(c + 1, s ^ 1);
            issueB(c + 1, s ^ 1);
            CP_COMMIT();
            CP_WAIT(1);
        } else {
            CP_WAIT(0);
        }
        __syncthreads();

        const uint32_t aB = sb + s * STAGE;
        const uint32_t bB = aB + APLANE;

        const int rowL = lane & 15;
        const uint32_t xorA = (uint32_t)((rowL & 7) << 4);
        const uint32_t colA0 = (uint32_t)((lane >> 4) * 16);
        const int nl = ((lane >> 4) << 3) + (lane & 7);
        const uint32_t xorB = (uint32_t)((nl & 7) << 4);
        const uint32_t colB0 = (uint32_t)(((lane >> 3) & 1) * 16);

#pragma unroll
        for (int s16 = 0; s16 < 4; ++s16) {
#pragma unroll
            for (int mth = 0; mth < 2; ++mth) {
                uint32_t af[2][4];
#pragma unroll
                for (int q = 0; q < 2; ++q) {
                    const int mt = mth * 2 + q;
                    const uint32_t off = (uint32_t)(warpM + mt * 16 + rowL) * 128 +
                                         ((colA0 + s16 * 32) ^ xorA);
                    ldsm4(af[q][0], af[q][1], af[q][2], af[q][3], aB + off);
                }
#pragma unroll
                for (int np = 0; np < NT / 2; ++np) {
                    const uint32_t offB = (uint32_t)(warpN + np * 16 + nl) * 128 +
                                          ((colB0 + s16 * 32) ^ xorB);
                    uint32_t b0, b1, b2, b3;
                    ldsm4(b0, b1, b2, b3, bB + offB);
#pragma unroll
                    for (int q = 0; q < 2; ++q)
                        mma16816(acc[mth * 2 + q][2 * np], af[q], b0, b1);
#pragma unroll
                    for (int q = 0; q < 2; ++q)
                        mma16816(acc[mth * 2 + q][2 * np + 1], af[q], b2, b3);
                }
            }
        }
        __syncthreads();
    }

    // epilogue: write C (fp16) + per-column stats
    const int g = lane >> 2, tig = lane & 3;
#pragma unroll
    for (int mt = 0; mt < 4; ++mt) {
#pragma unroll
        for (int nt = 0; nt < NT; ++nt) {
            const int row = row0 + warpM + mt * 16 + g;
            const int col = warpN + nt * 8 + tig * 2;
            *(uint32_t*)(C + (size_t)row * NOUT + col) =
                h2bits(__floats2half2_rn(acc[mt][nt][0], acc[mt][nt][1]));
            *(uint32_t*)(C + (size_t)(row + 8) * NOUT + col) =
                h2bits(__floats2half2_rn(acc[mt][nt][2], acc[mt][nt][3]));
        }
    }
#pragma unroll
    for (int nt = 0; nt < NT; ++nt) {
        float s0 = 0.f, s1 = 0.f, q0 = 0.f, q1 = 0.f;
#pragma unroll
        for (int mt = 0; mt < 4; ++mt) {
            const float a0 = acc[mt][nt][0], a1 = acc[mt][nt][1];
            const float a2 = acc[mt][nt][2], a3 = acc[mt][nt][3];
            s0 += a0 + a2;  s1 += a1 + a3;
            q0 += a0 * a0 + a2 * a2;
            q1 += a1 * a1 + a3 * a3;
        }
#pragma unroll
        for (int o = 4; o < 32; o <<= 1) {
            s0 += __shfl_xor_sync(~0u, s0, o);
            s1 += __shfl_xor_sync(~0u, s1, o);
            q0 += __shfl_xor_sync(~0u, q0, o);
            q1 += __shfl_xor_sync(~0u, q1, o);
        }
        if (g == 0) {
            const int col = warpN + nt * 8 + tig * 2;
            atomicAdd(&sS[col], s0);  atomicAdd(&sS[col + 1], s1);
            atomicAdd(&sQ[col], q0);  atomicAdd(&sQ[col + 1], q1);
        }
    }
    __syncthreads();
    if (t < NOUT) {
        atomicAdd(statS + b * NOUT + t, sS[t]);
        atomicAdd(statQ + b * NOUT + t, sQ[t]);
        __threadfence();
    }
    __syncthreads();

    __shared__ int sLast;
    if (t == 0) sLast = (atomicAdd(&counter[b], 1) == 63);
    __syncthreads();
    if (sLast && t < NOUT) {
        const float s = *(volatile float*)(statS + b * NOUT + t);
        const float q = *(volatile float*)(statQ + b * NOUT + t);
        float gs = s, gq = q;
#pragma unroll
        for (int o = CPG >> 1; o; o >>= 1) {
            gs += __shfl_xor_sync(~0u, gs, o);
            gq += __shfl_xor_sync(~0u, gq, o);
        }
        const float cnt = (float)N1 * (float)CPG;
        const float mean = gs / cnt;
        const float var  = gq / cnt - mean * mean;
        const float rstd = rsqrtf(var + 1e-5f);
        const float sc = rstd * gw[t];
        oScale[b * NOUT + t] = sc;
        oShift[b * NOUT + t] = gb[t] - mean * sc;
    }
}

// ---------------- GEMM2 persistent: GN0-fold A, GEMM, stats, sync, apply ----
// out[m,n] = relu_gn1( sum_k relu(gn0(h1))[m,k] * w1[n,k] )
// 148 CTAs x 512 threads, each handles 3-4 tiles of 128 rows, then a
// grid-wide sync (all CTAs resident) and in-kernel GN1+ReLU apply.
__global__ __launch_bounds__(512, 1) void gemm2_persist(
    const __half* __restrict__ Af, const __half* __restrict__ Bh,
    float* __restrict__ C,
    const float* __restrict__ scale, const float* __restrict__ shift,
    float* __restrict__ statS, float* __restrict__ statQ,
    const float* __restrict__ gw, const float* __restrict__ gb,
    int* __restrict__ doneCnt)
{
    constexpr int K = H0, NOUT = H1;       // 256, 128
    constexpr int CH = K / 64;             // 4
    constexpr int WN = NOUT / 8;           // 16
    constexpr int NT = WN / 8;             // 2
    constexpr int APLANE = 16384;
    constexpr int BCHUNK = 16384;          // 128 rows x 128B per K-chunk
    constexpr int NTILES = NPTS / 128;     // 512

    extern __shared__ __align__(128) char smem[];
    const uint32_t sb = smem_u32(smem);
    const uint32_t AS = sb;                 // 2 x 16KB
    const uint32_t BS = sb + 2 * APLANE;    // 4 x 16KB (all of w1)
    float* sS     = (float*)(smem + 2 * APLANE + 4 * BCHUNK);
    float* sQ     = sS + NOUT;
    float* sScale = sQ + NOUT;              // [K]
    float* sShift = sScale + K;
    float* sAsc   = sShift + K;             // [NOUT] apply scale
    float* sAsh   = sAsc + NOUT;

    const int t = threadIdx.x;
    const int wid = t >> 5, lane = t & 31;
    const int warpM = (wid >> 3) * 64;
    const int warpN = (wid & 7) * WN;

    // ---- load ALL of B (w1: 128 x 256 fp16 = 64KB) once ----
    for (int i = t; i < 4096; i += 512) {
        const int n = i >> 5, rest = i & 31;
        const int c = rest >> 3, a = rest & 7;
        const uint32_t swo = (uint32_t)(a * 16) ^ (uint32_t)((n & 7) << 4);
        cpa16(BS + c * BCHUNK + n * 128 + swo,
              Bh + (size_t)n * K + c * 64 + a * 8);
    }
    CP_COMMIT(); CP_WAIT(0);
    __syncthreads();

    int myTiles[4];
    int nMine = 0;
    float va[2][8];

    for (int tile = blockIdx.x; tile < NTILES; tile += NSM) {
        myTiles[nMine++] = tile;
        const int row0 = tile * 128;
        const int b = row0 >> 13;

        if (t < NOUT) { sS[t] = 0.f; sQ[t] = 0.f; }
        if (t < K) { sScale[t] = scale[b * K + t]; sShift[t] = shift[b * K + t]; }
        __syncthreads();

        float acc[4][NT][4];
#pragma unroll
        for (int i = 0; i < 4; ++i)
#pragma unroll
            for (int j = 0; j < NT; ++j)
#pragma unroll
                for (int q = 0; q < 4; ++q) acc[i][j][q] = 0.f;

        auto ldgA = [&](int c) {
#pragma unroll
            for (int i = 0; i < 2; ++i) {
                const int id = t + i * 512;
                const int r = id >> 3, a = id & 7;
                const uint4 raw = *(const uint4*)(Af + (size_t)(row0 + r) * K + c * 64 + a * 8);
                const __half2* hp = (const __half2*)&raw;
                const float2 f0 = __half22float2(hp[0]);
                const float2 f1 = __half22float2(hp[1]);
                const float2 f2 = __half22float2(hp[2]);
                const float2 f3 = __half22float2(hp[3]);
                const int col = c * 64 + a * 8;
                const float4 s0 = *(const float4*)(sScale + col);
                const float4 s1 = *(const float4*)(sScale + col + 4);
                const float4 h0 = *(const float4*)(sShift + col);
                const float4 h1 = *(const float4*)(sShift + col + 4);
                va[i][0] = fmaxf(0.f, fmaf(f0.x, s0.x, h0.x));
                va[i][1] = fmaxf(0.f, fmaf(f0.y, s0.y, h0.y));
                va[i][2] = fmaxf(0.f, fmaf(f1.x, s0.z, h0.z));
                va[i][3] = fmaxf(0.f, fmaf(f1.y, s0.w, h0.w));
                va[i][4] = fmaxf(0.f, fmaf(f2.x, s1.x, h1.x));
                va[i][5] = fmaxf(0.f, fmaf(f2.y, s1.y, h1.y));
                va[i][6] = fmaxf(0.f, fmaf(f3.x, s1.z, h1.z));
                va[i][7] = fmaxf(0.f, fmaf(f3.y, s1.w, h1.w));
            }
        };
        auto stsA = [&](int s) {
#pragma unroll
            for (int i = 0; i < 2; ++i) {
                const int id = t + i * 512;
                const int r = id >> 3, a = id & 7;
                uint32_t hw[4];
#pragma unroll
                for (int q = 0; q < 4; ++q)
                    hw[q] = h2bits(__floats2half2_rn(va[i][2 * q], va[i][2 * q + 1]));
                const uint32_t swo = (uint32_t)(a * 16) ^ (uint32_t)((r & 7) << 4);
                asm volatile("st.shared.v4.b32 [%0], {%1,%2,%3,%4};"
                             :: "r"(AS + s * APLANE + r * 128 + swo),
                                "r"(hw[0]), "r"(hw[1]), "r"(hw[2]), "r"(hw[3]) : "memory");
            }
        };

        ldgA(0);
        for (int c = 0; c < CH; ++c) {
            const int s = c & 1;
            stsA(s);
            __syncthreads();
            if (c + 1 < CH) ldgA(c + 1);

            const uint32_t aB = AS + s * APLANE;
            const uint32_t bB = BS + c * BCHUNK;

            const int rowL = lane & 15;
            const uint32_t xorA = (uint32_t)((rowL & 7) << 4);
            const uint32_t colA0 = (uint32_t)((lane >> 4) * 16);
            const int nl = ((lane >> 4) << 3) + (lane & 7);
            const uint32_t xorB = (uint32_t)((nl & 7) << 4);
            const uint32_t colB0 = (uint32_t)(((lane >> 3) & 1) * 16);

#pragma unroll
            for (int s16 = 0; s16 < 4; ++s16) {
#pragma unroll
                for (int mth = 0; mth < 2; ++mth) {
                    uint32_t af[2][4];
#pragma unroll
                    for (int q = 0; q < 2; ++q) {
                        const int mt = mth * 2 + q;
                        const uint32_t off = (uint32_t)(warpM + mt * 16 + rowL) * 128 +
                                             ((colA0 + s16 * 32) ^ xorA);
                        ldsm4(af[q][0], af[q][1], af[q][2], af[q][3], aB + off);
                    }
                    const uint32_t offB = (uint32_t)(warpN + nl) * 128 +
                                          ((colB0 + s16 * 32) ^ xorB);
                    uint32_t b0, b1, b2, b3;
                    ldsm4(b0, b1, b2, b3, bB + offB);
#pragma unroll
                    for (int q = 0; q < 2; ++q)
                        mma16816(acc[mth * 2 + q][0], af[q], b0, b1);
#pragma unroll
                    for (int q = 0; q < 2; ++q)
                        mma16816(acc[mth * 2 + q][1], af[q], b2, b3);
                }
            }
            __syncthreads();
        }

        // epilogue: write C (fp32) + stats
        const int g = lane >> 2, tig = lane & 3;
#pragma unroll
        for (int mt = 0; mt < 4; ++mt) {
#pragma unroll
            for (int nt = 0; nt < NT; ++nt) {
                const int row = row0 + warpM + mt * 16 + g;
                const int col = warpN + nt * 8 + tig * 2;
                *(float2*)(C + (size_t)row * NOUT + col) =
                    make_float2(acc[mt][nt][0], acc[mt][nt][1]);
                *(float2*)(C + (size_t)(row + 8) * NOUT + col) =
                    make_float2(acc[mt][nt][2], acc[mt][nt][3]);
            }
        }
#pragma unroll
        for (int nt = 0; nt < NT; ++nt) {
            float s0 = 0.f, s1 = 0.f, q0 = 0.f, q1 = 0.f;
#pragma unroll
            for (int mt = 0; mt < 4; ++mt) {
                const float a0 = acc[mt][nt][0], a1 = acc[mt][nt][1];
                const float a2 = acc[mt][nt][2], a3 = acc[mt][nt][3];
                s0 += a0 + a2;  s1 += a1 + a3;
                q0 += a0 * a0 + a2 * a2;
                q1 += a1 * a1 + a3 * a3;
            }
#pragma unroll
            for (int o = 4; o < 32; o <<= 1) {
                s0 += __shfl_xor_sync(~0u, s0, o);
                s1 += __shfl_xor_sync(~0u, s1, o);
                q0 += __shfl_xor_sync(~0u, q0, o);
                q1 += __shfl_xor_sync(~0u, q1, o);
            }
            if (g == 0) {
                const int col = warpN + nt * 8 + tig * 2;
                atomicAdd(&sS[col], s0);  atomicAdd(&sS[col + 1], s1);
                atomicAdd(&sQ[col], q0);  atomicAdd(&sQ[col + 1], q1);
            }
        }
        __syncthreads();
        if (t < NOUT) {
            atomicAdd(statS + b * NOUT + t, sS[t]);
            atomicAdd(statQ + b * NOUT + t, sQ[t]);
        }
        __syncthreads();
    }

    // ---- grid-wide sync (all 148 CTAs resident -> deadlock-free) ----
    __threadfence();
    __syncthreads();
    if (t == 0) {
        atomicAdd(doneCnt, 1);
        while (*(volatile int*)doneCnt < NSM) { }
    }
    __syncthreads();
    __threadfence();

    // ---- apply GN1 + ReLU to owned tiles (L2-resident) ----
    for (int i = 0; i < nMine; ++i) {
        const int tile = myTiles[i];
        const int row0 = tile * 128;
        const int b = row0 >> 13;
        if (t < NOUT) {
            float gs = *(volatile float*)(statS + b * NOUT + t);
            float gq = *(volatile float*)(statQ + b * NOUT + t);
            gs += __shfl_xor_sync(~0u, gs, 1);
            gs += __shfl_xor_sync(~0u, gs, 2);
            gq += __shfl_xor_sync(~0u, gq, 1);
            gq += __shfl_xor_sync(~0u, gq, 2);
            const float cnt = (float)N1 * 4.0f;
            const float mean = gs / cnt;
            const float var  = gq / cnt - mean * mean;
            const float rstd = rsqrtf(var + 1e-5f);
            const float sc = rstd * gw[t];
            sAsc[t] = sc;
            sAsh[t] = gb[t] - mean * sc;
        }
        __syncthreads();
#pragma unroll
        for (int k = 0; k < 8; ++k) {
            const int e = t + k * 512;         // 4096 float4 per tile
            const int r = e >> 5, c4 = e & 31;
            float* p = C + (size_t)(row0 + r) * NOUT + c4 * 4;
            const float4 sc = *(const float4*)(sAsc + c4 * 4);
            const float4 sh = *(const float4*)(sAsh + c4 * 4);
            float4 v = *(float4*)p;
            v.x = fmaxf(0.f, fmaf(v.x, sc.x, sh.x));
            v.y = fmaxf(0.f, fmaf(v.y, sc.y, sh.y));
            v.z = fmaxf(0.f, fmaf(v.z, sc.z, sh.z));
            v.w = fmaxf(0.f, fmaf(v.w, sc.w, sh.w));
            *(float4*)p = v;
        }
        __syncthreads();
    }
}

// ---------------- knn + interpolate (R9 geometry: 256 thr / 256 pts) --------
__global__ __launch_bounds__(256) void knn_interp_kernel(
    const float* __restrict__ xyz1, const float* __restrict__ xyz2,
    const float* __restrict__ points1, const float* __restrict__ points2,
    const float* __restrict__ w0src, const float* __restrict__ w1src)
{
    const int b = blockIdx.y;

    if (blockIdx.x == N1 / 256) {   // prep slice: weights + zero accums
        const int t = threadIdx.x;
        for (int i = b * (H0 * CIN / BB) + t; i < (b + 1) * (H0 * CIN / BB); i += 256)
            g_w0h[i] = __float2half_rn(w0src[i]);
        for (int i = b * (H1 * H0 / BB) + t; i < (b + 1) * (H1 * H0 / BB); i += 256)
            g_w1h[i] = __float2half_rn(w1src[i]);
        if (b == 0) {
            for (int i = t; i < BB * H0; i += 256) { g_s0[i] = 0.f; g_q0[i] = 0.f; }
            for (int i = t; i < BB * H1; i += 256) { g_s1[i] = 0.f; g_q1[i] = 0.f; }
            if (t < BB) g_cnt0[t] = 0;
            if (t == 0) g_done = 0;
        }
        return;
    }

    __shared__ float4 sp[M2];                        // 32 KB
    __shared__ float sW0[256], sW1[256], sW2[256];
    __shared__ int   sI0[256], sI1[256], sI2[256];
    const float* x2 = xyz2 + (size_t)b * M2 * 3;
    for (int j = threadIdx.x; j < M2; j += 256) {
        float x = x2[j * 3 + 0], y = x2[j * 3 + 1], z = x2[j * 3 + 2];
        sp[j] = make_float4(-2.f * x, -2.f * y, -2.f * z, x * x + y * y + z * z);
    }
    __syncthreads();

    const int n = blockIdx.x * 256 + threadIdx.x;
    const float* p1 = xyz1 + ((size_t)b * N1 + n) * 3;
    const float px = p1[0], py = p1[1], pz = p1[2];
    const float psq = px * px + py * py + pz * pz;

    float d0 = 1e30f, d1 = 1e30f, d2 = 1e30f;
    int i0 = 0, i1 = 0, i2 = 0;
    auto insert = [&](float d, int j) {
        if (d < d2) {
            if (d < d1) {
                if (d < d0) { d2 = d1; i2 = i1; d1 = d0; i1 = i0; d0 = d; i0 = j; }
                else        { d2 = d1; i2 = i1; d1 = d;  i1 = j; }
            } else          { d2 = d;  i2 = j; }
        }
    };
#pragma unroll 4
    for (int j = 0; j < M2; j += 2) {
        const float4 qa = sp[j];
        const float4 qb = sp[j + 1];
        const float da = fmaf(px, qa.x, fmaf(py, qa.y, fmaf(pz, qa.z, qa.w)));
        const float db = fmaf(px, qb.x, fmaf(py, qb.y, fmaf(pz, qb.z, qb.w)));
        if (fminf(da, db) < d2) { insert(da, j); insert(db, j + 1); }
    }

    {
        float w0 = 1.0f / ((d0 + psq) + 1e-8f);
        float w1 = 1.0f / ((d1 + psq) + 1e-8f);
        float w2 = 1.0f / ((d2 + psq) + 1e-8f);
        const float inv = 1.0f / (w0 + w1 + w2);
        sW0[threadIdx.x] = w0 * inv;
        sW1[threadIdx.x] = w1 * inv;
        sW2[threadIdx.x] = w2 * inv;
        sI0[threadIdx.x] = i0;
        sI1[threadIdx.x] = i1;
        sI2[threadIdx.x] = i2;
    }
    __syncthreads();

    // warp-cooperative gather + interpolate + concat
    const int lane = threadIdx.x & 31, w = threadIdx.x >> 5;
    const size_t mbase = (size_t)b * N1 + blockIdx.x * 256;
    const float* p2base = points2 + (size_t)b * M2 * C2;

#pragma unroll 4
    for (int pp = 0; pp < 32; ++pp) {
        const int p = w * 32 + pp;
        const size_t m = mbase + p;
        __half* fhp = g_fh + m * CIN;

        const float4 u = *(const float4*)(points1 + m * C1 + lane * 4);
        const uint32_t c01 = h2bits(__floats2half2_rn(u.x, u.y));
        const uint32_t c23 = h2bits(__floats2half2_rn(u.z, u.w));
        *(uint2*)(fhp + lane * 4) = make_uint2(c01, c23);

        const float w0 = sW0[p], w1 = sW1[p], w2 = sW2[p];
        const float* r0 = p2base + (size_t)sI0[p] * C2 + lane * 8;
        const float* r1 = p2base + (size_t)sI1[p] * C2 + lane * 8;
        const float* r2 = p2base + (size_t)sI2[p] * C2 + lane * 8;
        uint32_t oh[4];
#pragma unroll
        for (int h = 0; h < 2; ++h) {
            const float4 a  = *(const float4*)(r0 + h * 4);
            const float4 bb = *(const float4*)(r1 + h * 4);
            const float4 cc = *(const float4*)(r2 + h * 4);
            const float o0 = w0 * a.x + w1 * bb.x + w2 * cc.x;
            const float o1 = w0 * a.y + w1 * bb.y + w2 * cc.y;
            const float o2 = w0 * a.z + w1 * bb.z + w2 * cc.z;
            const float o3 = w0 * a.w + w1 * bb.w + w2 * cc.w;
            oh[h * 2 + 0] = h2bits(__floats2half2_rn(o0, o1));
            oh[h * 2 + 1] = h2bits(__floats2half2_rn(o2, o3));
        }
        *(uint4*)(fhp + C1 + lane * 8) = make_uint4(oh[0], oh[1], oh[2], oh[3]);
    }
}

// ---------------- launcher ---------------------------------------------------
extern "C" void kernel_launch(void* const* d_in, const int* in_sizes, int n_in,
                              void* d_out, int out_size)
{
    const float* xyz1    = (const float*)d_in[0];
    const float* xyz2    = (const float*)d_in[1];
    const float* points1 = (const float*)d_in[2];
    const float* points2 = (const float*)d_in[3];
    const float* w0      = (const float*)d_in[4];
    const float* w1      = (const float*)d_in[5];
    const float* gn0w    = (const float*)d_in[6];
    const float* gn0b    = (const float*)d_in[7];
    const float* gn1w    = (const float*)d_in[8];
    const float* gn1b    = (const float*)d_in[9];
    float* out = (float*)d_out;

    __half *fh, *w0h, *w1h, *h1;
    float *sc0, *sh0, *s0, *q0, *s1, *q1;
    int *c0, *done;
    cudaGetSymbolAddress((void**)&fh,  g_fh);
    cudaGetSymbolAddress((void**)&w0h, g_w0h);
    cudaGetSymbolAddress((void**)&w1h, g_w1h);
    cudaGetSymbolAddress((void**)&h1,  g_h1);
    cudaGetSymbolAddress((void**)&sc0, g_scale0);
    cudaGetSymbolAddress((void**)&sh0, g_shift0);
    cudaGetSymbolAddress((void**)&s0,  g_s0);
    cudaGetSymbolAddress((void**)&q0,  g_q0);
    cudaGetSymbolAddress((void**)&s1,  g_s1);
    cudaGetSymbolAddress((void**)&q1,  g_q1);
    cudaGetSymbolAddress((void**)&c0,  g_cnt0);
    cudaGetSymbolAddress((void**)&done, g_done);

    const int SMEM1 = 2 * (16384 + H0 * 128) + 2 * H0 * 4;             // 100352
    const int SMEM2 = 2 * 16384 + 4 * 16384 + (2 * H1 + 2 * H0 + 2 * H1) * 4;  // ~101.4KB
    cudaFuncSetAttribute(mma_gemm1,
                         cudaFuncAttributeMaxDynamicSharedMemorySize, SMEM1);
    cudaFuncSetAttribute(gemm2_persist,
                         cudaFuncAttributeMaxDynamicSharedMemorySize, SMEM2);

    // 1) knn interp + concat; last x-column does weight prep + zeroing
    knn_interp_kernel<<<dim3(N1 / 256 + 1, BB), 256>>>(
        xyz1, xyz2, points1, points2, w0, w1);

    // 2) h1(fp16) = feat @ w0^T; fused GN0 stats + scale fold
    mma_gemm1<<<NPTS / 128, 512, SMEM1>>>(
        fh, w0h, h1, s0, q0, gn0w, gn0b, sc0, sh0, c0);

    // 3) persistent: out = relu(gn0(h1)) @ w1^T, GN1 stats, grid-sync,
    //    GN1+ReLU apply in-kernel
    gemm2_persist<<<NSM, 512, SMEM2>>>(
        h1, w1h, out, sc0, sh0, s1, q1, gn1w, gn1b, done);
}